// round 1
// baseline (speedup 1.0000x reference)
#include <cuda_runtime.h>
#include <math.h>

// Problem constants
#define BQ    2        // batch
#define CC    128      // channels (Ci)
#define NSP   32768    // spatial d = 32*32*32
#define LSEQ  128      // language length
#define CTX   768      // language channels (Ct)
#define NHEAD 4
#define HDIM  32       // head dim

// ---------------- scratch (device globals: allocation-free) ----------------
__device__ float g_q   [BQ*CC*NSP];   // q pre-norm (b,c,n)
__device__ float g_skip[BQ*CC*NSP];   // skip pre-norm (b,c,n)
__device__ float g_x   [BQ*CC*NSP];   // attention out, x_bdc layout [b][n][ci] == weight_in flat
__device__ float g_w   [BQ*CC*NSP];   // weight pre-norm (b,c,n)
__device__ float g_o   [BQ*CC*NSP];   // out (post relu)
__device__ float g_t   [BQ*CC*NSP];   // relu(conv(out, wg1))
__device__ float g_k   [BQ*CC*LSEQ];
__device__ float g_v   [BQ*CC*LSEQ];
__device__ float g_mu  [3*BQ*CC];     // slot0=q, slot1=skip, slot2=weight
__device__ float g_rs  [3*BQ*CC];

// ---------------- SGEMM: out[b][o][n] = sum_c W[o][c]*X[b][c][n] + bias[o] ----------------
// INPROD: X := norm(X)*norm(X2) elementwise (for skip*weight)
// EPI: 0 none, 1 relu, 2 tanh(.)*outmul -> out  (final gate fuse)
template<int INPROD, int EPI>
__global__ __launch_bounds__(256) void gemm_kernel(
    const float* __restrict__ X, const float* __restrict__ X2,
    const float* __restrict__ mu1, const float* __restrict__ rs1,
    const float* __restrict__ mu2, const float* __restrict__ rs2,
    const float* __restrict__ W, const float* __restrict__ bias,
    const float* __restrict__ outmul, float* __restrict__ out)
{
    constexpr int KCH = 32;
    __shared__ float Wt[KCH][132];   // Wt[k][o], padded (row = 528B, 16B aligned)
    __shared__ float Xs[KCH][132];   // Xs[k][n]
    const int b  = blockIdx.y;
    const int n0 = blockIdx.x * 128;
    const int tid = threadIdx.x;
    const int tx = tid & 15;         // n-group
    const int ty = tid >> 4;         // o-group
    float acc[8][8];
#pragma unroll
    for (int i = 0; i < 8; i++)
#pragma unroll
        for (int j = 0; j < 8; j++) acc[i][j] = 0.f;
    const size_t xbase = (size_t)b * CC * NSP;

    for (int k0 = 0; k0 < CC; k0 += KCH) {
        // load W chunk transposed: Wt[kk][o] = W[o][k0+kk]
        for (int i = tid; i < KCH*128; i += 256) {
            int o = i >> 5, kk = i & 31;
            Wt[kk][o] = W[o*CC + k0 + kk];
        }
        // load X chunk: Xs[kk][n]
        for (int i = tid; i < KCH*128; i += 256) {
            int kk = i >> 7, n = i & 127;
            int c = k0 + kk;
            size_t gi = xbase + (size_t)c*NSP + n0 + n;
            float xv;
            if (INPROD) {
                int sc = b*CC + c;
                float s  = (X [gi] - mu1[sc]) * rs1[sc];
                float w2 = (X2[gi] - mu2[sc]) * rs2[sc];
                xv = s * w2;
            } else {
                xv = X[gi];
            }
            Xs[kk][n] = xv;
        }
        __syncthreads();
#pragma unroll
        for (int kk = 0; kk < KCH; kk++) {
            float a[8], bb[8];
#pragma unroll
            for (int i = 0; i < 8; i++) a[i]  = Wt[kk][ty*8 + i];
#pragma unroll
            for (int j = 0; j < 8; j++) bb[j] = Xs[kk][tx*8 + j];
#pragma unroll
            for (int i = 0; i < 8; i++)
#pragma unroll
                for (int j = 0; j < 8; j++) acc[i][j] = fmaf(a[i], bb[j], acc[i][j]);
        }
        __syncthreads();
    }

#pragma unroll
    for (int i = 0; i < 8; i++) {
        int o = ty*8 + i;
        float bi = bias[o];
        size_t ob = xbase + (size_t)o*NSP + n0 + tx*8;
#pragma unroll
        for (int j = 0; j < 8; j++) {
            float v = acc[i][j] + bi;
            if (EPI == 1) v = fmaxf(v, 0.f);
            if (EPI == 2) v = tanhf(v) * outmul[ob + j];
            out[ob + j] = v;
        }
    }
}

// ---------------- instance-norm stats: mean & rsqrt(var+eps) per (b,c) over 32768 ----------------
__global__ __launch_bounds__(256) void stats_kernel(const float* __restrict__ buf,
                                                    float* __restrict__ mu, float* __restrict__ rs)
{
    int bc = blockIdx.x;  // 0..BQ*CC-1
    const float4* p = reinterpret_cast<const float4*>(buf + (size_t)bc * NSP);
    float s = 0.f, s2 = 0.f;
    for (int i = threadIdx.x; i < NSP/4; i += 256) {
        float4 v = p[i];
        s  += v.x + v.y + v.z + v.w;
        s2 += v.x*v.x + v.y*v.y + v.z*v.z + v.w*v.w;
    }
#pragma unroll
    for (int off = 16; off > 0; off >>= 1) {
        s  += __shfl_down_sync(0xffffffffu, s,  off);
        s2 += __shfl_down_sync(0xffffffffu, s2, off);
    }
    __shared__ float sha[8], shb[8];
    int lane = threadIdx.x & 31, wid = threadIdx.x >> 5;
    if (lane == 0) { sha[wid] = s; shb[wid] = s2; }
    __syncthreads();
    if (threadIdx.x == 0) {
        float ts = 0.f, ts2 = 0.f;
        for (int w = 0; w < 8; w++) { ts += sha[w]; ts2 += shb[w]; }
        float mean = ts * (1.f/NSP);
        float var  = ts2 * (1.f/NSP) - mean*mean;
        mu[bc] = mean;
        rs[bc] = rsqrtf(var + 1e-5f);
    }
}

// ---------------- k/v projections: (B,Ci,L) = wk/wv @ lang + b, * mask ----------------
__global__ __launch_bounds__(128) void kv_kernel(const float* __restrict__ lang,
                                                 const float* __restrict__ mask,
                                                 const float* __restrict__ wk, const float* __restrict__ bk,
                                                 const float* __restrict__ wv, const float* __restrict__ bv)
{
    int b = blockIdx.y, o = blockIdx.x, l = threadIdx.x;
    const float* lp  = lang + (size_t)b*CTX*LSEQ + l;
    const float* wkr = wk + (size_t)o*CTX;
    const float* wvr = wv + (size_t)o*CTX;
    float ak = 0.f, av = 0.f;
    for (int c = 0; c < CTX; c++) {
        float x = lp[(size_t)c*LSEQ];
        ak = fmaf(wkr[c], x, ak);
        av = fmaf(wvr[c], x, av);
    }
    float m = mask[b*LSEQ + l];
    g_k[(b*CC + o)*LSEQ + l] = (ak + bk[o]) * m;
    g_v[(b*CC + o)*LSEQ + l] = (av + bv[o]) * m;
}

// ---------------- attention: softmax((norm(q)*scale) @ k + bias) @ v^T ----------------
// one thread per query point; k/v tiles in smem (warp-uniform broadcast reads)
#define ATTN_SMEM_FLOATS (2*HDIM*LSEQ + HDIM + HDIM + LSEQ + 128*(LSEQ+1))
__global__ __launch_bounds__(128) void attn_kernel(const float* __restrict__ qbuf,
                                                   const float* __restrict__ mask)
{
    extern __shared__ float sm[];
    float* ks   = sm;                    // [32][128]
    float* vs   = ks + HDIM*LSEQ;        // [32][128]
    float* qmu  = vs + HDIM*LSEQ;        // [32]
    float* qrs  = qmu + HDIM;            // [32]
    float* mb   = qrs + HDIM;            // [128]
    float* simb = mb + LSEQ;             // [128][129]
    int bh = blockIdx.y;
    int b = bh >> 2, h = bh & 3;
    int n0 = blockIdx.x * 128;
    int t = threadIdx.x;

    for (int i = t; i < HDIM*LSEQ; i += 128) {
        int idx = (b*CC + h*HDIM + (i >> 7))*LSEQ + (i & 127);
        ks[i] = g_k[idx];
        vs[i] = g_v[idx];
    }
    if (t < HDIM) {
        int ch = b*CC + h*HDIM + t;          // q stats are slot 0
        qmu[t] = g_mu[ch];
        qrs[t] = g_rs[ch] * 0.17677669529663687f;  // fold hd^-0.5 into q
    }
    mb[t] = 10000.f * mask[b*LSEQ + t] - 10000.f;
    __syncthreads();

    int n = n0 + t;
    float qv[HDIM];
#pragma unroll
    for (int c = 0; c < HDIM; c++)
        qv[c] = (qbuf[(size_t)(b*CC + h*HDIM + c)*NSP + n] - qmu[c]) * qrs[c];

    float* srow = simb + t*(LSEQ+1);
    float mx = -1e30f;
    for (int l = 0; l < LSEQ; l++) {
        float s = mb[l];
#pragma unroll
        for (int c = 0; c < HDIM; c++) s = fmaf(qv[c], ks[c*LSEQ + l], s);
        srow[l] = s;
        mx = fmaxf(mx, s);
    }
    float ssum = 0.f;
    for (int l = 0; l < LSEQ; l++) { float e = __expf(srow[l] - mx); srow[l] = e; ssum += e; }
    float inv = 1.f / ssum;

    float xa[HDIM];
#pragma unroll
    for (int c = 0; c < HDIM; c++) xa[c] = 0.f;
    for (int l = 0; l < LSEQ; l++) {
        float p = srow[l];
#pragma unroll
        for (int c = 0; c < HDIM; c++) xa[c] = fmaf(p, vs[c*LSEQ + l], xa[c]);
    }
    // x_bdc layout: [b][n][ci], ci fastest
    float* op = g_x + ((size_t)b*NSP + n)*CC + h*HDIM;
#pragma unroll
    for (int c = 0; c < HDIM; c += 4) {
        float4 v4 = make_float4(xa[c]*inv, xa[c+1]*inv, xa[c+2]*inv, xa[c+3]*inv);
        *reinterpret_cast<float4*>(op + c) = v4;
    }
}

// ---------------- host orchestration ----------------
extern "C" void kernel_launch(void* const* d_in, const int* in_sizes, int n_in,
                              void* d_out, int out_size)
{
    const float* img  = (const float*)d_in[0];
    const float* lang = (const float*)d_in[1];
    const float* mask = (const float*)d_in[2];
    const float* wq   = (const float*)d_in[3];
    const float* bq   = (const float*)d_in[4];
    const float* wk   = (const float*)d_in[5];
    const float* bk   = (const float*)d_in[6];
    const float* wv   = (const float*)d_in[7];
    const float* bv   = (const float*)d_in[8];
    const float* wpw  = (const float*)d_in[9];
    const float* bpw  = (const float*)d_in[10];
    const float* wpi  = (const float*)d_in[11];
    const float* bpi  = (const float*)d_in[12];
    const float* wpo  = (const float*)d_in[13];
    const float* bpo  = (const float*)d_in[14];
    const float* wg1  = (const float*)d_in[15];
    const float* bg1  = (const float*)d_in[16];
    const float* wg2  = (const float*)d_in[17];
    const float* bg2  = (const float*)d_in[18];
    float* out = (float*)d_out;

    void *pq, *pskip, *px, *pw, *po, *pt, *pmu, *prs;
    cudaGetSymbolAddress(&pq,   g_q);
    cudaGetSymbolAddress(&pskip,g_skip);
    cudaGetSymbolAddress(&px,   g_x);
    cudaGetSymbolAddress(&pw,   g_w);
    cudaGetSymbolAddress(&po,   g_o);
    cudaGetSymbolAddress(&pt,   g_t);
    cudaGetSymbolAddress(&pmu,  g_mu);
    cudaGetSymbolAddress(&prs,  g_rs);
    float* Q    = (float*)pq;
    float* SKIP = (float*)pskip;
    float* X    = (float*)px;
    float* WB   = (float*)pw;
    float* O    = (float*)po;
    float* T    = (float*)pt;
    float* MU   = (float*)pmu;
    float* RS   = (float*)prs;

    const int attn_smem = ATTN_SMEM_FLOATS * (int)sizeof(float);
    cudaFuncSetAttribute(attn_kernel, cudaFuncAttributeMaxDynamicSharedMemorySize, attn_smem);

    dim3 gg(NSP/128, BQ);

    // q_pre = wq@img + bq ; skip_pre = wpi@img + bpi
    gemm_kernel<0,0><<<gg,256>>>(img, nullptr, nullptr,nullptr,nullptr,nullptr, wq,  bq,  nullptr, Q);
    gemm_kernel<0,0><<<gg,256>>>(img, nullptr, nullptr,nullptr,nullptr,nullptr, wpi, bpi, nullptr, SKIP);
    stats_kernel<<<BQ*CC,256>>>(Q,    MU + 0,       RS + 0);        // slot 0: q
    stats_kernel<<<BQ*CC,256>>>(SKIP, MU + BQ*CC,   RS + BQ*CC);    // slot 1: skip

    kv_kernel<<<dim3(CC,BQ),128>>>(lang, mask, wk, bk, wv, bv);

    // attention (applies q norm + scale on the fly), writes x_bdc layout
    attn_kernel<<<dim3(NSP/128, BQ*NHEAD), 128, attn_smem>>>(Q, mask);

    // weight_pre = wpw @ weight_in (weight_in == g_x reinterpreted) + bpw
    gemm_kernel<0,0><<<gg,256>>>(X, nullptr, nullptr,nullptr,nullptr,nullptr, wpw, bpw, nullptr, WB);
    stats_kernel<<<BQ*CC,256>>>(WB, MU + 2*BQ*CC, RS + 2*BQ*CC);    // slot 2: weight

    // out = relu(wpo @ (norm(skip)*norm(weight)) + bpo)
    gemm_kernel<1,1><<<gg,256>>>(SKIP, WB, MU + BQ*CC, RS + BQ*CC, MU + 2*BQ*CC, RS + 2*BQ*CC,
                                 wpo, bpo, nullptr, O);
    // t = relu(wg1 @ out + bg1)
    gemm_kernel<0,1><<<gg,256>>>(O, nullptr, nullptr,nullptr,nullptr,nullptr, wg1, bg1, nullptr, T);
    // final = tanh(wg2 @ t + bg2) * out
    gemm_kernel<0,2><<<gg,256>>>(T, nullptr, nullptr,nullptr,nullptr,nullptr, wg2, bg2, O, out);
}

// round 2
// speedup vs baseline: 1.6050x; 1.6050x over previous
#include <cuda_runtime.h>
#include <math.h>
#include <stdint.h>

// Problem constants
#define BQ    2        // batch
#define CC    128      // channels (Ci)
#define NSP   32768    // spatial d = 32*32*32
#define LSEQ  128      // language length
#define CTX   768      // language channels (Ct)
#define NHEAD 4
#define HDIM  32       // head dim

// ---------------- scratch (device globals: allocation-free) ----------------
__device__ float g_q   [BQ*CC*NSP];
__device__ float g_skip[BQ*CC*NSP];
__device__ float g_x   [BQ*CC*NSP];   // attention out, x_bdc layout [b][n][ci] == weight_in flat
__device__ float g_w   [BQ*CC*NSP];
__device__ float g_o   [BQ*CC*NSP];
__device__ float g_t   [BQ*CC*NSP];
__device__ float g_k   [BQ*CC*LSEQ];
__device__ float g_v   [BQ*CC*LSEQ];
__device__ float g_mu  [3*BQ*CC];
__device__ float g_rs  [3*BQ*CC];

__device__ __forceinline__ uint32_t f2tf32(float f) {
    uint32_t r;
    asm("cvt.rna.tf32.f32 %0, %1;" : "=r"(r) : "f"(f));
    return r;
}

__device__ __forceinline__ void mma_tf32(float c[4], const uint32_t a[4], const uint32_t b[2]) {
    asm volatile(
        "mma.sync.aligned.m16n8k8.row.col.f32.tf32.tf32.f32 "
        "{%0,%1,%2,%3}, {%4,%5,%6,%7}, {%8,%9}, {%0,%1,%2,%3};"
        : "+f"(c[0]), "+f"(c[1]), "+f"(c[2]), "+f"(c[3])
        : "r"(a[0]), "r"(a[1]), "r"(a[2]), "r"(a[3]), "r"(b[0]), "r"(b[1]));
}

// ---------------- tensor-core SGEMM (tf32): out[b][o][n] = W@X + bias ----------------
// INPROD: X := norm(X)*norm(X2) elementwise (skip*weight)
// EPI: 0 none, 1 relu, 2 tanh(.)*outmul
#define SPAD 136   // row pitch in floats; 136%32==8 -> conflict-free fragment gathers
template<int INPROD, int EPI>
__global__ __launch_bounds__(256, 2) void gemm_tc(
    const float* __restrict__ X, const float* __restrict__ X2,
    const float* __restrict__ mu1, const float* __restrict__ rs1,
    const float* __restrict__ mu2, const float* __restrict__ rs2,
    const float* __restrict__ W, const float* __restrict__ bias,
    const float* __restrict__ outmul, float* __restrict__ out)
{
    __shared__ uint32_t sW[32][SPAD];   // sW[k][o]  (tf32 bits)
    __shared__ uint32_t sX[32][SPAD];   // sX[k][n]
    const int b   = blockIdx.y;
    const int n0  = blockIdx.x * 128;
    const int tid = threadIdx.x;
    const int lane = tid & 31;
    const int wid  = tid >> 5;
    const int wm = (wid >> 2) * 64;   // warp row base (o)
    const int wn = (wid & 3) * 32;    // warp col base (n)
    const size_t xbase = (size_t)b * CC * NSP;

    float acc[4][4][4];
#pragma unroll
    for (int mi = 0; mi < 4; mi++)
#pragma unroll
        for (int ni = 0; ni < 4; ni++)
#pragma unroll
            for (int r = 0; r < 4; r++) acc[mi][ni][r] = 0.f;

    for (int k0 = 0; k0 < CC; k0 += 32) {
        // ---- stage W chunk: sW[kk][o] = tf32(W[o][k0+kk]) ----
        {
            int o = tid >> 1;                 // 0..127
            int qh = tid & 1;                 // which half of the 8 quads
            const float4* wp = reinterpret_cast<const float4*>(W + o*CC + k0);
#pragma unroll
            for (int j = 0; j < 4; j++) {
                int kq = qh*4 + j;
                float4 w4 = wp[kq];
                int kk = kq*4;
                sW[kk+0][o] = f2tf32(w4.x);
                sW[kk+1][o] = f2tf32(w4.y);
                sW[kk+2][o] = f2tf32(w4.z);
                sW[kk+3][o] = f2tf32(w4.w);
            }
        }
        // ---- stage X chunk: sX[kk][n] = tf32(x) ----
        {
            int n4  = (tid & 31) * 4;
            int kkb = tid >> 5;               // 0..7
#pragma unroll
            for (int r = 0; r < 4; r++) {
                int kk = kkb + 8*r;
                int c  = k0 + kk;
                size_t gi = xbase + (size_t)c*NSP + n0 + n4;
                float4 v = *reinterpret_cast<const float4*>(X + gi);
                if (INPROD) {
                    int sc = b*CC + c;
                    float m1 = mu1[sc], r1 = rs1[sc], m2 = mu2[sc], r2 = rs2[sc];
                    float4 v2 = *reinterpret_cast<const float4*>(X2 + gi);
                    v.x = ((v.x - m1)*r1) * ((v2.x - m2)*r2);
                    v.y = ((v.y - m1)*r1) * ((v2.y - m2)*r2);
                    v.z = ((v.z - m1)*r1) * ((v2.z - m2)*r2);
                    v.w = ((v.w - m1)*r1) * ((v2.w - m2)*r2);
                }
                uint4 u = make_uint4(f2tf32(v.x), f2tf32(v.y), f2tf32(v.z), f2tf32(v.w));
                *reinterpret_cast<uint4*>(&sX[kk][n4]) = u;
            }
        }
        __syncthreads();

#pragma unroll
        for (int k8 = 0; k8 < 32; k8 += 8) {
            uint32_t af[4][4], bf[4][2];
#pragma unroll
            for (int mi = 0; mi < 4; mi++) {
                int o = wm + mi*16 + (lane >> 2);
                int k = k8 + (lane & 3);
                af[mi][0] = sW[k  ][o  ];
                af[mi][1] = sW[k  ][o+8];
                af[mi][2] = sW[k+4][o  ];
                af[mi][3] = sW[k+4][o+8];
            }
#pragma unroll
            for (int ni = 0; ni < 4; ni++) {
                int n = wn + ni*8 + (lane >> 2);
                int k = k8 + (lane & 3);
                bf[ni][0] = sX[k  ][n];
                bf[ni][1] = sX[k+4][n];
            }
#pragma unroll
            for (int mi = 0; mi < 4; mi++)
#pragma unroll
                for (int ni = 0; ni < 4; ni++)
                    mma_tf32(acc[mi][ni], af[mi], bf[ni]);
        }
        __syncthreads();
    }

    // ---- epilogue ----
#pragma unroll
    for (int mi = 0; mi < 4; mi++) {
        int o  = wm + mi*16 + (lane >> 2);
        float bi0 = bias[o];
        float bi1 = bias[o+8];
#pragma unroll
        for (int ni = 0; ni < 4; ni++) {
            int n = n0 + wn + ni*8 + (lane & 3)*2;
            size_t i0 = xbase + (size_t)o*NSP + n;
            size_t i1 = i0 + (size_t)8*NSP;
            float v0 = acc[mi][ni][0] + bi0;
            float v1 = acc[mi][ni][1] + bi0;
            float v2 = acc[mi][ni][2] + bi1;
            float v3 = acc[mi][ni][3] + bi1;
            if (EPI == 1) {
                v0 = fmaxf(v0, 0.f); v1 = fmaxf(v1, 0.f);
                v2 = fmaxf(v2, 0.f); v3 = fmaxf(v3, 0.f);
            }
            if (EPI == 2) {
                float2 m0 = *reinterpret_cast<const float2*>(outmul + i0);
                float2 m1 = *reinterpret_cast<const float2*>(outmul + i1);
                v0 = tanhf(v0) * m0.x; v1 = tanhf(v1) * m0.y;
                v2 = tanhf(v2) * m1.x; v3 = tanhf(v3) * m1.y;
            }
            *reinterpret_cast<float2*>(out + i0) = make_float2(v0, v1);
            *reinterpret_cast<float2*>(out + i1) = make_float2(v2, v3);
        }
    }
}

// ---------------- instance-norm stats ----------------
__global__ __launch_bounds__(256) void stats_kernel(const float* __restrict__ buf,
                                                    float* __restrict__ mu, float* __restrict__ rs)
{
    int bc = blockIdx.x;
    const float4* p = reinterpret_cast<const float4*>(buf + (size_t)bc * NSP);
    float s = 0.f, s2 = 0.f;
    for (int i = threadIdx.x; i < NSP/4; i += 256) {
        float4 v = p[i];
        s  += v.x + v.y + v.z + v.w;
        s2 += v.x*v.x + v.y*v.y + v.z*v.z + v.w*v.w;
    }
#pragma unroll
    for (int off = 16; off > 0; off >>= 1) {
        s  += __shfl_down_sync(0xffffffffu, s,  off);
        s2 += __shfl_down_sync(0xffffffffu, s2, off);
    }
    __shared__ float sha[8], shb[8];
    int lane = threadIdx.x & 31, wid = threadIdx.x >> 5;
    if (lane == 0) { sha[wid] = s; shb[wid] = s2; }
    __syncthreads();
    if (threadIdx.x == 0) {
        float ts = 0.f, ts2 = 0.f;
        for (int w = 0; w < 8; w++) { ts += sha[w]; ts2 += shb[w]; }
        float mean = ts * (1.f/NSP);
        float var  = ts2 * (1.f/NSP) - mean*mean;
        mu[bc] = mean;
        rs[bc] = rsqrtf(var + 1e-5f);
    }
}

// ---------------- k/v projections ----------------
__global__ __launch_bounds__(128) void kv_kernel(const float* __restrict__ lang,
                                                 const float* __restrict__ mask,
                                                 const float* __restrict__ wk, const float* __restrict__ bk,
                                                 const float* __restrict__ wv, const float* __restrict__ bv)
{
    int b = blockIdx.y, o = blockIdx.x, l = threadIdx.x;
    const float* lp  = lang + (size_t)b*CTX*LSEQ + l;
    const float* wkr = wk + (size_t)o*CTX;
    const float* wvr = wv + (size_t)o*CTX;
    float ak = 0.f, av = 0.f;
    for (int c = 0; c < CTX; c++) {
        float x = lp[(size_t)c*LSEQ];
        ak = fmaf(wkr[c], x, ak);
        av = fmaf(wvr[c], x, av);
    }
    float m = mask[b*LSEQ + l];
    g_k[(b*CC + o)*LSEQ + l] = (ak + bk[o]) * m;
    g_v[(b*CC + o)*LSEQ + l] = (av + bv[o]) * m;
}

// ---------------- attention ----------------
#define ATTN_SMEM_FLOATS (2*HDIM*LSEQ + HDIM + HDIM + LSEQ + 128*(LSEQ+1))
__global__ __launch_bounds__(128) void attn_kernel(const float* __restrict__ qbuf,
                                                   const float* __restrict__ mask)
{
    extern __shared__ float sm[];
    float* ks   = sm;
    float* vs   = ks + HDIM*LSEQ;
    float* qmu  = vs + HDIM*LSEQ;
    float* qrs  = qmu + HDIM;
    float* mb   = qrs + HDIM;
    float* simb = mb + LSEQ;
    int bh = blockIdx.y;
    int b = bh >> 2, h = bh & 3;
    int n0 = blockIdx.x * 128;
    int t = threadIdx.x;

    for (int i = t; i < HDIM*LSEQ; i += 128) {
        int idx = (b*CC + h*HDIM + (i >> 7))*LSEQ + (i & 127);
        ks[i] = g_k[idx];
        vs[i] = g_v[idx];
    }
    if (t < HDIM) {
        int ch = b*CC + h*HDIM + t;
        qmu[t] = g_mu[ch];
        qrs[t] = g_rs[ch] * 0.17677669529663687f;
    }
    mb[t] = 10000.f * mask[b*LSEQ + t] - 10000.f;
    __syncthreads();

    int n = n0 + t;
    float qv[HDIM];
#pragma unroll
    for (int c = 0; c < HDIM; c++)
        qv[c] = (qbuf[(size_t)(b*CC + h*HDIM + c)*NSP + n] - qmu[c]) * qrs[c];

    float* srow = simb + t*(LSEQ+1);
    float mx = -1e30f;
    for (int l = 0; l < LSEQ; l++) {
        float s = mb[l];
#pragma unroll
        for (int c = 0; c < HDIM; c++) s = fmaf(qv[c], ks[c*LSEQ + l], s);
        srow[l] = s;
        mx = fmaxf(mx, s);
    }
    float ssum = 0.f;
    for (int l = 0; l < LSEQ; l++) { float e = __expf(srow[l] - mx); srow[l] = e; ssum += e; }
    float inv = 1.f / ssum;

    float xa[HDIM];
#pragma unroll
    for (int c = 0; c < HDIM; c++) xa[c] = 0.f;
    for (int l = 0; l < LSEQ; l++) {
        float p = srow[l];
#pragma unroll
        for (int c = 0; c < HDIM; c++) xa[c] = fmaf(p, vs[c*LSEQ + l], xa[c]);
    }
    float* op = g_x + ((size_t)b*NSP + n)*CC + h*HDIM;
#pragma unroll
    for (int c = 0; c < HDIM; c += 4) {
        float4 v4 = make_float4(xa[c]*inv, xa[c+1]*inv, xa[c+2]*inv, xa[c+3]*inv);
        *reinterpret_cast<float4*>(op + c) = v4;
    }
}

// ---------------- host orchestration ----------------
extern "C" void kernel_launch(void* const* d_in, const int* in_sizes, int n_in,
                              void* d_out, int out_size)
{
    const float* img  = (const float*)d_in[0];
    const float* lang = (const float*)d_in[1];
    const float* mask = (const float*)d_in[2];
    const float* wq   = (const float*)d_in[3];
    const float* bq   = (const float*)d_in[4];
    const float* wk   = (const float*)d_in[5];
    const float* bk   = (const float*)d_in[6];
    const float* wv   = (const float*)d_in[7];
    const float* bv   = (const float*)d_in[8];
    const float* wpw  = (const float*)d_in[9];
    const float* bpw  = (const float*)d_in[10];
    const float* wpi  = (const float*)d_in[11];
    const float* bpi  = (const float*)d_in[12];
    const float* wpo  = (const float*)d_in[13];
    const float* bpo  = (const float*)d_in[14];
    const float* wg1  = (const float*)d_in[15];
    const float* bg1  = (const float*)d_in[16];
    const float* wg2  = (const float*)d_in[17];
    const float* bg2  = (const float*)d_in[18];
    float* out = (float*)d_out;

    void *pq, *pskip, *px, *pw, *po, *pt, *pmu, *prs;
    cudaGetSymbolAddress(&pq,   g_q);
    cudaGetSymbolAddress(&pskip,g_skip);
    cudaGetSymbolAddress(&px,   g_x);
    cudaGetSymbolAddress(&pw,   g_w);
    cudaGetSymbolAddress(&po,   g_o);
    cudaGetSymbolAddress(&pt,   g_t);
    cudaGetSymbolAddress(&pmu,  g_mu);
    cudaGetSymbolAddress(&prs,  g_rs);
    float* Q    = (float*)pq;
    float* SKIP = (float*)pskip;
    float* X    = (float*)px;
    float* WB   = (float*)pw;
    float* O    = (float*)po;
    float* T    = (float*)pt;
    float* MU   = (float*)pmu;
    float* RS   = (float*)prs;

    const int attn_smem = ATTN_SMEM_FLOATS * (int)sizeof(float);
    cudaFuncSetAttribute(attn_kernel, cudaFuncAttributeMaxDynamicSharedMemorySize, attn_smem);

    dim3 gg(NSP/128, BQ);

    gemm_tc<0,0><<<gg,256>>>(img, nullptr, nullptr,nullptr,nullptr,nullptr, wq,  bq,  nullptr, Q);
    gemm_tc<0,0><<<gg,256>>>(img, nullptr, nullptr,nullptr,nullptr,nullptr, wpi, bpi, nullptr, SKIP);
    stats_kernel<<<BQ*CC,256>>>(Q,    MU + 0,       RS + 0);
    stats_kernel<<<BQ*CC,256>>>(SKIP, MU + BQ*CC,   RS + BQ*CC);

    kv_kernel<<<dim3(CC,BQ),128>>>(lang, mask, wk, bk, wv, bv);

    attn_kernel<<<dim3(NSP/128, BQ*NHEAD), 128, attn_smem>>>(Q, mask);

    gemm_tc<0,0><<<gg,256>>>(X, nullptr, nullptr,nullptr,nullptr,nullptr, wpw, bpw, nullptr, WB);
    stats_kernel<<<BQ*CC,256>>>(WB, MU + 2*BQ*CC, RS + 2*BQ*CC);

    gemm_tc<1,1><<<gg,256>>>(SKIP, WB, MU + BQ*CC, RS + BQ*CC, MU + 2*BQ*CC, RS + 2*BQ*CC,
                             wpo, bpo, nullptr, O);
    gemm_tc<0,1><<<gg,256>>>(O, nullptr, nullptr,nullptr,nullptr,nullptr, wg1, bg1, nullptr, T);
    gemm_tc<0,2><<<gg,256>>>(T, nullptr, nullptr,nullptr,nullptr,nullptr, wg2, bg2, O, out);
}

// round 3
// speedup vs baseline: 2.5011x; 1.5583x over previous
#include <cuda_runtime.h>
#include <math.h>
#include <stdint.h>

// Problem constants
#define BQ    2        // batch
#define CC    128      // channels (Ci)
#define NSP   32768    // spatial d = 32*32*32
#define LSEQ  128      // language length
#define CTX   768      // language channels (Ct)
#define NHEAD 4
#define HDIM  32       // head dim
#define NBLK  256      // spatial blocks (NSP/128)

// ---------------- scratch (device globals: allocation-free) ----------------
__device__ float g_q   [BQ*CC*NSP];
__device__ float g_skip[BQ*CC*NSP];
__device__ float g_x   [BQ*CC*NSP];   // attention out, [b][n][ci] flat == weight_in flat
__device__ float g_w   [BQ*CC*NSP];
__device__ float g_k   [BQ*CC*LSEQ];
__device__ float g_v   [BQ*CC*LSEQ];
__device__ float g_mu  [3*BQ*CC];     // slot0=q, slot1=skip, slot2=weight
__device__ float g_rs  [3*BQ*CC];
__device__ float g_ps  [3*BQ*CC*NBLK];   // per-block partial sums
__device__ float g_pq2 [3*BQ*CC*NBLK];   // per-block partial sumsq

__device__ __forceinline__ uint32_t f2tf32(float f) {
    uint32_t r;
    asm("cvt.rna.tf32.f32 %0, %1;" : "=r"(r) : "f"(f));
    return r;
}

__device__ __forceinline__ void mma_tf32(float c[4], const uint32_t a[4], const uint32_t b[2]) {
    asm volatile(
        "mma.sync.aligned.m16n8k8.row.col.f32.tf32.tf32.f32 "
        "{%0,%1,%2,%3}, {%4,%5,%6,%7}, {%8,%9}, {%0,%1,%2,%3};"
        : "+f"(c[0]), "+f"(c[1]), "+f"(c[2]), "+f"(c[3])
        : "r"(a[0]), "r"(a[1]), "r"(a[2]), "r"(a[3]), "r"(b[0]), "r"(b[1]));
}

#define SPAD 136   // row pitch in 32-bit words; 136%32==8 -> conflict-free fragment gathers

// stage one 32-K chunk of weights (row-major [o][c]) transposed into sW[k][o]
__device__ __forceinline__ void stage_w(uint32_t* sW, const float* __restrict__ W, int k0, int tid) {
    int o  = tid >> 1;
    int qh = tid & 1;
    const float4* wp = reinterpret_cast<const float4*>(W + o*CC + k0);
#pragma unroll
    for (int j = 0; j < 4; j++) {
        int kq = qh*4 + j;
        float4 w4 = wp[kq];
        int kk = kq*4;
        sW[(kk+0)*SPAD + o] = f2tf32(w4.x);
        sW[(kk+1)*SPAD + o] = f2tf32(w4.y);
        sW[(kk+2)*SPAD + o] = f2tf32(w4.z);
        sW[(kk+3)*SPAD + o] = f2tf32(w4.w);
    }
}

// ---------------- producer GEMM: out[b][o][n] = W@X + bias, + per-channel stats partials ----------
__global__ __launch_bounds__(256, 2) void gemm_tc(
    const float* __restrict__ X,
    const float* __restrict__ W, const float* __restrict__ bias,
    float* __restrict__ out, float* __restrict__ ps, float* __restrict__ pq)
{
    __shared__ uint32_t sW[32*SPAD];
    __shared__ uint32_t sX[32*SPAD];
    __shared__ float redS[CC][4];
    __shared__ float redQ[CC][4];
    const int b   = blockIdx.y;
    const int n0  = blockIdx.x * 128;
    const int tid = threadIdx.x;
    const int lane = tid & 31;
    const int wid  = tid >> 5;
    const int wm = (wid >> 2) * 64;
    const int wn = (wid & 3) * 32;
    const size_t xbase = (size_t)b * CC * NSP;

    float acc[4][4][4];
#pragma unroll
    for (int mi = 0; mi < 4; mi++)
#pragma unroll
        for (int ni = 0; ni < 4; ni++)
#pragma unroll
            for (int r = 0; r < 4; r++) acc[mi][ni][r] = 0.f;

    for (int k0 = 0; k0 < CC; k0 += 32) {
        stage_w(sW, W, k0, tid);
        {
            int n4  = (tid & 31) * 4;
            int kkb = tid >> 5;
#pragma unroll
            for (int r = 0; r < 4; r++) {
                int kk = kkb + 8*r;
                size_t gi = xbase + (size_t)(k0+kk)*NSP + n0 + n4;
                float4 v = *reinterpret_cast<const float4*>(X + gi);
                uint4 u = make_uint4(f2tf32(v.x), f2tf32(v.y), f2tf32(v.z), f2tf32(v.w));
                *reinterpret_cast<uint4*>(&sX[kk*SPAD + n4]) = u;
            }
        }
        __syncthreads();
#pragma unroll
        for (int k8 = 0; k8 < 32; k8 += 8) {
            uint32_t af[4][4], bf[4][2];
#pragma unroll
            for (int mi = 0; mi < 4; mi++) {
                int o = wm + mi*16 + (lane >> 2);
                int k = k8 + (lane & 3);
                af[mi][0] = sW[k*SPAD + o];
                af[mi][1] = sW[k*SPAD + o+8];
                af[mi][2] = sW[(k+4)*SPAD + o];
                af[mi][3] = sW[(k+4)*SPAD + o+8];
            }
#pragma unroll
            for (int ni = 0; ni < 4; ni++) {
                int n = wn + ni*8 + (lane >> 2);
                int k = k8 + (lane & 3);
                bf[ni][0] = sX[k*SPAD + n];
                bf[ni][1] = sX[(k+4)*SPAD + n];
            }
#pragma unroll
            for (int mi = 0; mi < 4; mi++)
#pragma unroll
                for (int ni = 0; ni < 4; ni++)
                    mma_tf32(acc[mi][ni], af[mi], bf[ni]);
        }
        __syncthreads();
    }

    // epilogue + stats partials
    float sL[4], qL[4], sH[4], qH[4];
#pragma unroll
    for (int mi = 0; mi < 4; mi++) { sL[mi]=0.f; qL[mi]=0.f; sH[mi]=0.f; qH[mi]=0.f; }
#pragma unroll
    for (int mi = 0; mi < 4; mi++) {
        int o  = wm + mi*16 + (lane >> 2);
        float bi0 = bias[o];
        float bi1 = bias[o+8];
#pragma unroll
        for (int ni = 0; ni < 4; ni++) {
            int n = n0 + wn + ni*8 + (lane & 3)*2;
            size_t i0 = xbase + (size_t)o*NSP + n;
            size_t i1 = i0 + (size_t)8*NSP;
            float v0 = acc[mi][ni][0] + bi0;
            float v1 = acc[mi][ni][1] + bi0;
            float v2 = acc[mi][ni][2] + bi1;
            float v3 = acc[mi][ni][3] + bi1;
            sL[mi] += v0+v1; qL[mi] += v0*v0+v1*v1;
            sH[mi] += v2+v3; qH[mi] += v2*v2+v3*v3;
            *reinterpret_cast<float2*>(out + i0) = make_float2(v0, v1);
            *reinterpret_cast<float2*>(out + i1) = make_float2(v2, v3);
        }
    }
#pragma unroll
    for (int mi = 0; mi < 4; mi++) {
        sL[mi] += __shfl_xor_sync(0xffffffffu, sL[mi], 1);
        sL[mi] += __shfl_xor_sync(0xffffffffu, sL[mi], 2);
        qL[mi] += __shfl_xor_sync(0xffffffffu, qL[mi], 1);
        qL[mi] += __shfl_xor_sync(0xffffffffu, qL[mi], 2);
        sH[mi] += __shfl_xor_sync(0xffffffffu, sH[mi], 1);
        sH[mi] += __shfl_xor_sync(0xffffffffu, sH[mi], 2);
        qH[mi] += __shfl_xor_sync(0xffffffffu, qH[mi], 1);
        qH[mi] += __shfl_xor_sync(0xffffffffu, qH[mi], 2);
    }
    if ((lane & 3) == 0) {
        int col = wid & 3;
        int rg  = lane >> 2;
#pragma unroll
        for (int mi = 0; mi < 4; mi++) {
            int r = wm + mi*16 + rg;
            redS[r][col] = sL[mi]; redQ[r][col] = qL[mi];
            redS[r+8][col] = sH[mi]; redQ[r+8][col] = qH[mi];
        }
    }
    __syncthreads();
    if (tid < CC) {
        float s = redS[tid][0]+redS[tid][1]+redS[tid][2]+redS[tid][3];
        float q = redQ[tid][0]+redQ[tid][1]+redQ[tid][2]+redQ[tid][3];
        int bc = b*CC + tid;
        ps[bc*NBLK + blockIdx.x] = s;
        pq[bc*NBLK + blockIdx.x] = q;
    }
}

// ---------------- finalize stats: reduce 256 partials per channel ----------------
__global__ __launch_bounds__(256) void finalize_kernel(const float* __restrict__ ps,
                                                       const float* __restrict__ pq,
                                                       float* __restrict__ mu, float* __restrict__ rs)
{
    int e = blockIdx.x, t = threadIdx.x;
    float s = ps[e*NBLK + t];
    float q = pq[e*NBLK + t];
#pragma unroll
    for (int off = 16; off > 0; off >>= 1) {
        s += __shfl_down_sync(0xffffffffu, s, off);
        q += __shfl_down_sync(0xffffffffu, q, off);
    }
    __shared__ float sa[8], sb[8];
    int lane = t & 31, wid = t >> 5;
    if (lane == 0) { sa[wid] = s; sb[wid] = q; }
    __syncthreads();
    if (t == 0) {
        float ts = 0.f, tq = 0.f;
        for (int w = 0; w < 8; w++) { ts += sa[w]; tq += sb[w]; }
        float mean = ts * (1.f/NSP);
        float var  = tq * (1.f/NSP) - mean*mean;
        mu[e] = mean;
        rs[e] = rsqrtf(var + 1e-5f);
    }
}

// ---------------- k/v projections ----------------
__global__ __launch_bounds__(128) void kv_kernel(const float* __restrict__ lang,
                                                 const float* __restrict__ mask,
                                                 const float* __restrict__ wk, const float* __restrict__ bk,
                                                 const float* __restrict__ wv, const float* __restrict__ bv)
{
    int b = blockIdx.y, o = blockIdx.x, l = threadIdx.x;
    const float* lp  = lang + (size_t)b*CTX*LSEQ + l;
    const float* wkr = wk + (size_t)o*CTX;
    const float* wvr = wv + (size_t)o*CTX;
    float ak = 0.f, av = 0.f;
    for (int c = 0; c < CTX; c++) {
        float x = lp[(size_t)c*LSEQ];
        ak = fmaf(wkr[c], x, ak);
        av = fmaf(wvr[c], x, av);
    }
    float m = mask[b*LSEQ + l];
    g_k[(b*CC + o)*LSEQ + l] = (ak + bk[o]) * m;
    g_v[(b*CC + o)*LSEQ + l] = (av + bv[o]) * m;
}

// ---------------- attention ----------------
#define SROWP 132
#define ATTN_SMEM_FLOATS (2*HDIM*LSEQ + HDIM + HDIM + LSEQ + 128*SROWP)
__global__ __launch_bounds__(128) void attn_kernel(const float* __restrict__ qbuf,
                                                   const float* __restrict__ mask)
{
    extern __shared__ float sm[];
    float* ks   = sm;
    float* vs   = ks + HDIM*LSEQ;
    float* qmu  = vs + HDIM*LSEQ;
    float* qrs  = qmu + HDIM;
    float* mb   = qrs + HDIM;
    float* simb = mb + LSEQ;
    int bh = blockIdx.y;
    int b = bh >> 2, h = bh & 3;
    int n0 = blockIdx.x * 128;
    int t = threadIdx.x;

    for (int i = t; i < HDIM*LSEQ; i += 128) {
        int idx = (b*CC + h*HDIM + (i >> 7))*LSEQ + (i & 127);
        ks[i] = g_k[idx];
        vs[i] = g_v[idx];
    }
    if (t < HDIM) {
        int ch = b*CC + h*HDIM + t;
        qmu[t] = g_mu[ch];
        qrs[t] = g_rs[ch] * 0.17677669529663687f;   // fold hd^-0.5
    }
    mb[t] = 10000.f * mask[b*LSEQ + t] - 10000.f;
    __syncthreads();

    int n = n0 + t;
    float qv[HDIM];
#pragma unroll
    for (int c = 0; c < HDIM; c++)
        qv[c] = (qbuf[(size_t)(b*CC + h*HDIM + c)*NSP + n] - qmu[c]) * qrs[c];

    float* srow = simb + t*SROWP;
    float mx = -1e30f;
#pragma unroll 2
    for (int l0 = 0; l0 < LSEQ; l0 += 4) {
        float4 m4 = *reinterpret_cast<const float4*>(&mb[l0]);
        float s0 = m4.x, s1 = m4.y, s2 = m4.z, s3 = m4.w;
#pragma unroll
        for (int c = 0; c < HDIM; c++) {
            float4 k4 = *reinterpret_cast<const float4*>(&ks[c*LSEQ + l0]);
            float q = qv[c];
            s0 = fmaf(q, k4.x, s0); s1 = fmaf(q, k4.y, s1);
            s2 = fmaf(q, k4.z, s2); s3 = fmaf(q, k4.w, s3);
        }
        *reinterpret_cast<float4*>(&srow[l0]) = make_float4(s0, s1, s2, s3);
        mx = fmaxf(mx, fmaxf(fmaxf(s0, s1), fmaxf(s2, s3)));
    }
    float ssum = 0.f;
#pragma unroll
    for (int l0 = 0; l0 < LSEQ; l0 += 4) {
        float4 v = *reinterpret_cast<float4*>(&srow[l0]);
        v.x = __expf(v.x - mx); v.y = __expf(v.y - mx);
        v.z = __expf(v.z - mx); v.w = __expf(v.w - mx);
        *reinterpret_cast<float4*>(&srow[l0]) = v;
        ssum += v.x + v.y + v.z + v.w;
    }
    float inv = 1.f / ssum;

    float xa[HDIM];
#pragma unroll
    for (int c = 0; c < HDIM; c++) xa[c] = 0.f;
    for (int l0 = 0; l0 < LSEQ; l0 += 32) {
        float p[32];
#pragma unroll
        for (int j4 = 0; j4 < 8; j4++)
            *reinterpret_cast<float4*>(&p[j4*4]) = *reinterpret_cast<float4*>(&srow[l0 + j4*4]);
#pragma unroll
        for (int c = 0; c < HDIM; c++) {
            float a = xa[c];
#pragma unroll
            for (int j = 0; j < 32; j += 4) {
                float4 v4 = *reinterpret_cast<const float4*>(&vs[c*LSEQ + l0 + j]);
                a = fmaf(p[j],   v4.x, a); a = fmaf(p[j+1], v4.y, a);
                a = fmaf(p[j+2], v4.z, a); a = fmaf(p[j+3], v4.w, a);
            }
            xa[c] = a;
        }
    }
    float* op = g_x + ((size_t)b*NSP + n)*CC + h*HDIM;
#pragma unroll
    for (int c = 0; c < HDIM; c += 4) {
        float4 v4 = make_float4(xa[c]*inv, xa[c+1]*inv, xa[c+2]*inv, xa[c+3]*inv);
        *reinterpret_cast<float4*>(op + c) = v4;
    }
}

// ---------------- fused chain: out = relu(wpo@(ns*nw)+b); t = relu(wg1@out+b); final = tanh(wg2@t+b)*out
// all intermediates smem-resident (K = full 128 channels per CTA)
__device__ __forceinline__ void chain_frag_a(const uint32_t* sW, uint32_t af[4][4],
                                             int k8, int lane, int wm) {
#pragma unroll
    for (int mi = 0; mi < 4; mi++) {
        int o = wm + mi*16 + (lane >> 2);
        int k = k8 + (lane & 3);
        af[mi][0] = sW[k*SPAD + o];
        af[mi][1] = sW[k*SPAD + o+8];
        af[mi][2] = sW[(k+4)*SPAD + o];
        af[mi][3] = sW[(k+4)*SPAD + o+8];
    }
}

template<int BMODE>   // 0: B is tf32 bits; 1: B is float, convert on load
__device__ __forceinline__ void chain_gemm(const float* __restrict__ Wg, uint32_t* sW,
                                           const uint32_t* sBb, const float* sBf,
                                           float acc[4][4][4],
                                           int tid, int lane, int wm, int wn)
{
#pragma unroll
    for (int mi = 0; mi < 4; mi++)
#pragma unroll
        for (int ni = 0; ni < 4; ni++)
#pragma unroll
            for (int r = 0; r < 4; r++) acc[mi][ni][r] = 0.f;
    for (int k0 = 0; k0 < CC; k0 += 32) {
        stage_w(sW, Wg, k0, tid);
        __syncthreads();
#pragma unroll
        for (int k8 = 0; k8 < 32; k8 += 8) {
            uint32_t af[4][4], bf[4][2];
            chain_frag_a(sW, af, k8, lane, wm);
            int kg = k0 + k8 + (lane & 3);
#pragma unroll
            for (int ni = 0; ni < 4; ni++) {
                int n = wn + ni*8 + (lane >> 2);
                if (BMODE == 0) {
                    bf[ni][0] = sBb[kg*SPAD + n];
                    bf[ni][1] = sBb[(kg+4)*SPAD + n];
                } else {
                    bf[ni][0] = f2tf32(sBf[kg*SPAD + n]);
                    bf[ni][1] = f2tf32(sBf[(kg+4)*SPAD + n]);
                }
            }
#pragma unroll
            for (int mi = 0; mi < 4; mi++)
#pragma unroll
                for (int ni = 0; ni < 4; ni++)
                    mma_tf32(acc[mi][ni], af[mi], bf[ni]);
        }
        __syncthreads();
    }
}

__global__ __launch_bounds__(256) void chain_kernel(
    const float* __restrict__ SKIP, const float* __restrict__ WB,
    const float* __restrict__ mu1, const float* __restrict__ rs1,
    const float* __restrict__ mu2, const float* __restrict__ rs2,
    const float* __restrict__ wpo, const float* __restrict__ bpo,
    const float* __restrict__ wg1, const float* __restrict__ bg1,
    const float* __restrict__ wg2, const float* __restrict__ bg2,
    float* __restrict__ out)
{
    extern __shared__ char smraw[];
    uint32_t* sW = reinterpret_cast<uint32_t*>(smraw);                       // [32][136]
    uint32_t* sB = reinterpret_cast<uint32_t*>(smraw + 32*SPAD*4);           // [128][136] tf32
    float*    sO = reinterpret_cast<float*>   (smraw + (32+128)*SPAD*4);     // [128][136] fp32
    float*    sBf = reinterpret_cast<float*>(sB);

    const int b   = blockIdx.y;
    const int n0  = blockIdx.x * 128;
    const int tid = threadIdx.x;
    const int lane = tid & 31;
    const int wid  = tid >> 5;
    const int wm = (wid >> 2) * 64;
    const int wn = (wid & 3) * 32;
    const size_t xbase = (size_t)b * CC * NSP;

    // stage full-K input tile: sB = tf32(norm(SKIP)*norm(WB))
    {
        int n4  = (tid & 31) * 4;
        int kkb = tid >> 5;
#pragma unroll
        for (int r = 0; r < 16; r++) {
            int c = kkb + 8*r;
            size_t gi = xbase + (size_t)c*NSP + n0 + n4;
            int sc = b*CC + c;
            float m1 = mu1[sc], r1 = rs1[sc], m2 = mu2[sc], r2 = rs2[sc];
            float4 v  = *reinterpret_cast<const float4*>(SKIP + gi);
            float4 v2 = *reinterpret_cast<const float4*>(WB + gi);
            v.x = ((v.x - m1)*r1) * ((v2.x - m2)*r2);
            v.y = ((v.y - m1)*r1) * ((v2.y - m2)*r2);
            v.z = ((v.z - m1)*r1) * ((v2.z - m2)*r2);
            v.w = ((v.w - m1)*r1) * ((v2.w - m2)*r2);
            uint4 u = make_uint4(f2tf32(v.x), f2tf32(v.y), f2tf32(v.z), f2tf32(v.w));
            *reinterpret_cast<uint4*>(&sB[c*SPAD + n4]) = u;
        }
    }
    __syncthreads();

    float acc[4][4][4];

    // GEMM1: out = relu(wpo @ sB + bpo) -> sO (fp32)
    chain_gemm<0>(wpo, sW, sB, nullptr, acc, tid, lane, wm, wn);
#pragma unroll
    for (int mi = 0; mi < 4; mi++) {
        int o = wm + mi*16 + (lane >> 2);
        float bi0 = bpo[o], bi1 = bpo[o+8];
#pragma unroll
        for (int ni = 0; ni < 4; ni++) {
            int n = wn + ni*8 + (lane & 3)*2;
            sO[o*SPAD + n]     = fmaxf(acc[mi][ni][0] + bi0, 0.f);
            sO[o*SPAD + n+1]   = fmaxf(acc[mi][ni][1] + bi0, 0.f);
            sO[(o+8)*SPAD + n]   = fmaxf(acc[mi][ni][2] + bi1, 0.f);
            sO[(o+8)*SPAD + n+1] = fmaxf(acc[mi][ni][3] + bi1, 0.f);
        }
    }
    __syncthreads();

    // GEMM2: t = relu(wg1 @ sO + bg1) -> sB (tf32 bits, buffer reuse)
    chain_gemm<1>(wg1, sW, nullptr, sO, acc, tid, lane, wm, wn);
#pragma unroll
    for (int mi = 0; mi < 4; mi++) {
        int o = wm + mi*16 + (lane >> 2);
        float bi0 = bg1[o], bi1 = bg1[o+8];
#pragma unroll
        for (int ni = 0; ni < 4; ni++) {
            int n = wn + ni*8 + (lane & 3)*2;
            sB[o*SPAD + n]     = f2tf32(fmaxf(acc[mi][ni][0] + bi0, 0.f));
            sB[o*SPAD + n+1]   = f2tf32(fmaxf(acc[mi][ni][1] + bi0, 0.f));
            sB[(o+8)*SPAD + n]   = f2tf32(fmaxf(acc[mi][ni][2] + bi1, 0.f));
            sB[(o+8)*SPAD + n+1] = f2tf32(fmaxf(acc[mi][ni][3] + bi1, 0.f));
        }
    }
    __syncthreads();

    // GEMM3: final = tanh(wg2 @ sB + bg2) * sO -> global out
    chain_gemm<0>(wg2, sW, sB, nullptr, acc, tid, lane, wm, wn);
#pragma unroll
    for (int mi = 0; mi < 4; mi++) {
        int o = wm + mi*16 + (lane >> 2);
        float bi0 = bg2[o], bi1 = bg2[o+8];
#pragma unroll
        for (int ni = 0; ni < 4; ni++) {
            int n = wn + ni*8 + (lane & 3)*2;
            size_t i0 = xbase + (size_t)o*NSP + n0 + n;
            size_t i1 = i0 + (size_t)8*NSP;
            float v0 = tanhf(acc[mi][ni][0] + bi0) * sO[o*SPAD + n];
            float v1 = tanhf(acc[mi][ni][1] + bi0) * sO[o*SPAD + n+1];
            float v2 = tanhf(acc[mi][ni][2] + bi1) * sO[(o+8)*SPAD + n];
            float v3 = tanhf(acc[mi][ni][3] + bi1) * sO[(o+8)*SPAD + n+1];
            *reinterpret_cast<float2*>(out + i0) = make_float2(v0, v1);
            *reinterpret_cast<float2*>(out + i1) = make_float2(v2, v3);
        }
    }
}

// ---------------- host orchestration ----------------
extern "C" void kernel_launch(void* const* d_in, const int* in_sizes, int n_in,
                              void* d_out, int out_size)
{
    const float* img  = (const float*)d_in[0];
    const float* lang = (const float*)d_in[1];
    const float* mask = (const float*)d_in[2];
    const float* wq   = (const float*)d_in[3];
    const float* bq   = (const float*)d_in[4];
    const float* wk   = (const float*)d_in[5];
    const float* bk   = (const float*)d_in[6];
    const float* wv   = (const float*)d_in[7];
    const float* bv   = (const float*)d_in[8];
    const float* wpw  = (const float*)d_in[9];
    const float* bpw  = (const float*)d_in[10];
    const float* wpi  = (const float*)d_in[11];
    const float* bpi  = (const float*)d_in[12];
    const float* wpo  = (const float*)d_in[13];
    const float* bpo  = (const float*)d_in[14];
    const float* wg1  = (const float*)d_in[15];
    const float* bg1  = (const float*)d_in[16];
    const float* wg2  = (const float*)d_in[17];
    const float* bg2  = (const float*)d_in[18];
    float* out = (float*)d_out;

    void *pq, *pskip, *px, *pw, *pmu, *prs, *pps, *ppq;
    cudaGetSymbolAddress(&pq,   g_q);
    cudaGetSymbolAddress(&pskip,g_skip);
    cudaGetSymbolAddress(&px,   g_x);
    cudaGetSymbolAddress(&pw,   g_w);
    cudaGetSymbolAddress(&pmu,  g_mu);
    cudaGetSymbolAddress(&prs,  g_rs);
    cudaGetSymbolAddress(&pps,  g_ps);
    cudaGetSymbolAddress(&ppq,  g_pq2);
    float* Q    = (float*)pq;
    float* SKIP = (float*)pskip;
    float* X    = (float*)px;
    float* WB   = (float*)pw;
    float* MU   = (float*)pmu;
    float* RS   = (float*)prs;
    float* PS   = (float*)pps;
    float* PQ   = (float*)ppq;

    const int attn_smem  = ATTN_SMEM_FLOATS * (int)sizeof(float);
    const int chain_smem = (32 + 128)*SPAD*4 + 128*SPAD*4;   // sW + sB + sO
    cudaFuncSetAttribute(attn_kernel,  cudaFuncAttributeMaxDynamicSharedMemorySize, attn_smem);
    cudaFuncSetAttribute(chain_kernel, cudaFuncAttributeMaxDynamicSharedMemorySize, chain_smem);

    dim3 gg(NBLK, BQ);
    const int E = BQ*CC;   // entries per stats slot

    // producers (stats partials in epilogue)
    gemm_tc<<<gg,256>>>(img, wq,  bq,  Q,    PS + 0*E*NBLK, PQ + 0*E*NBLK);
    gemm_tc<<<gg,256>>>(img, wpi, bpi, SKIP, PS + 1*E*NBLK, PQ + 1*E*NBLK);
    finalize_kernel<<<2*E,256>>>(PS, PQ, MU, RS);           // slots 0,1

    kv_kernel<<<dim3(CC,BQ),128>>>(lang, mask, wk, bk, wv, bv);

    attn_kernel<<<dim3(NBLK, BQ*NHEAD), 128, attn_smem>>>(Q, mask);

    gemm_tc<<<gg,256>>>(X, wpw, bpw, WB, PS + 2*E*NBLK, PQ + 2*E*NBLK);
    finalize_kernel<<<E,256>>>(PS + 2*E*NBLK, PQ + 2*E*NBLK, MU + 2*E, RS + 2*E);   // slot 2

    chain_kernel<<<gg,256,chain_smem>>>(SKIP, WB,
                                        MU + 1*E, RS + 1*E, MU + 2*E, RS + 2*E,
                                        wpo, bpo, wg1, bg1, wg2, bg2, out);
}

// round 4
// speedup vs baseline: 2.8064x; 1.1221x over previous
#include <cuda_runtime.h>
#include <math.h>
#include <stdint.h>

// Problem constants
#define BQ    2        // batch
#define CC    128      // channels (Ci)
#define NSP   32768    // spatial d = 32*32*32
#define LSEQ  128      // language length
#define CTX   768      // language channels (Ct)
#define NHEAD 4
#define HDIM  32       // head dim
#define NBLK  256      // spatial blocks (NSP/128)
#define KVS   6        // kv split-K factor (768/128)

// ---------------- scratch (device globals: allocation-free) ----------------
__device__ float g_q   [BQ*CC*NSP];
__device__ float g_skip[BQ*CC*NSP];
__device__ float g_x   [BQ*CC*NSP];   // attention out, [b][n][ci] flat == weight_in flat
__device__ float g_w   [BQ*CC*NSP];
__device__ float g_k   [BQ*CC*LSEQ];
__device__ float g_v   [BQ*CC*LSEQ];
__device__ float g_kp  [BQ*KVS*CC*LSEQ];   // kv split-K partials
__device__ float g_vp  [BQ*KVS*CC*LSEQ];
__device__ float g_mu  [3*BQ*CC];     // slot0=q, slot1=skip, slot2=weight
__device__ float g_rs  [3*BQ*CC];
__device__ float g_ps  [3*BQ*CC*NBLK];   // per-block partial sums
__device__ float g_pq2 [3*BQ*CC*NBLK];   // per-block partial sumsq

__device__ __forceinline__ uint32_t f2tf32(float f) {
    uint32_t r;
    asm("cvt.rna.tf32.f32 %0, %1;" : "=r"(r) : "f"(f));
    return r;
}

__device__ __forceinline__ void mma_tf32(float c[4], const uint32_t a[4], const uint32_t b[2]) {
    asm volatile(
        "mma.sync.aligned.m16n8k8.row.col.f32.tf32.tf32.f32 "
        "{%0,%1,%2,%3}, {%4,%5,%6,%7}, {%8,%9}, {%0,%1,%2,%3};"
        : "+f"(c[0]), "+f"(c[1]), "+f"(c[2]), "+f"(c[3])
        : "r"(a[0]), "r"(a[1]), "r"(a[2]), "r"(a[3]), "r"(b[0]), "r"(b[1]));
}

#define SPAD 136   // row pitch in 32-bit words; 136%32==8 -> conflict-free fragment gathers

// stage one 32-K chunk of weights (row-major [o][c]) transposed into sW[k][o]
__device__ __forceinline__ void stage_w(uint32_t* sW, const float* __restrict__ W, int k0, int tid) {
    int o  = tid >> 1;
    int qh = tid & 1;
    const float4* wp = reinterpret_cast<const float4*>(W + o*CC + k0);
#pragma unroll
    for (int j = 0; j < 4; j++) {
        int kq = qh*4 + j;
        float4 w4 = wp[kq];
        int kk = kq*4;
        sW[(kk+0)*SPAD + o] = f2tf32(w4.x);
        sW[(kk+1)*SPAD + o] = f2tf32(w4.y);
        sW[(kk+2)*SPAD + o] = f2tf32(w4.z);
        sW[(kk+3)*SPAD + o] = f2tf32(w4.w);
    }
}

// ---------------- producer GEMM: out[b][o][n] = W@X + bias, + per-channel stats partials ----------
__global__ __launch_bounds__(256, 2) void gemm_tc(
    const float* __restrict__ X,
    const float* __restrict__ W, const float* __restrict__ bias,
    float* __restrict__ out, float* __restrict__ ps, float* __restrict__ pq)
{
    __shared__ uint32_t sW[32*SPAD];
    __shared__ uint32_t sX[32*SPAD];
    __shared__ float redS[CC][4];
    __shared__ float redQ[CC][4];
    const int b   = blockIdx.y;
    const int n0  = blockIdx.x * 128;
    const int tid = threadIdx.x;
    const int lane = tid & 31;
    const int wid  = tid >> 5;
    const int wm = (wid >> 2) * 64;
    const int wn = (wid & 3) * 32;
    const size_t xbase = (size_t)b * CC * NSP;

    float acc[4][4][4];
#pragma unroll
    for (int mi = 0; mi < 4; mi++)
#pragma unroll
        for (int ni = 0; ni < 4; ni++)
#pragma unroll
            for (int r = 0; r < 4; r++) acc[mi][ni][r] = 0.f;

    for (int k0 = 0; k0 < CC; k0 += 32) {
        stage_w(sW, W, k0, tid);
        {
            int n4  = (tid & 31) * 4;
            int kkb = tid >> 5;
#pragma unroll
            for (int r = 0; r < 4; r++) {
                int kk = kkb + 8*r;
                size_t gi = xbase + (size_t)(k0+kk)*NSP + n0 + n4;
                float4 v = *reinterpret_cast<const float4*>(X + gi);
                uint4 u = make_uint4(f2tf32(v.x), f2tf32(v.y), f2tf32(v.z), f2tf32(v.w));
                *reinterpret_cast<uint4*>(&sX[kk*SPAD + n4]) = u;
            }
        }
        __syncthreads();
#pragma unroll
        for (int k8 = 0; k8 < 32; k8 += 8) {
            uint32_t af[4][4], bf[4][2];
#pragma unroll
            for (int mi = 0; mi < 4; mi++) {
                int o = wm + mi*16 + (lane >> 2);
                int k = k8 + (lane & 3);
                af[mi][0] = sW[k*SPAD + o];
                af[mi][1] = sW[k*SPAD + o+8];
                af[mi][2] = sW[(k+4)*SPAD + o];
                af[mi][3] = sW[(k+4)*SPAD + o+8];
            }
#pragma unroll
            for (int ni = 0; ni < 4; ni++) {
                int n = wn + ni*8 + (lane >> 2);
                int k = k8 + (lane & 3);
                bf[ni][0] = sX[k*SPAD + n];
                bf[ni][1] = sX[(k+4)*SPAD + n];
            }
#pragma unroll
            for (int mi = 0; mi < 4; mi++)
#pragma unroll
                for (int ni = 0; ni < 4; ni++)
                    mma_tf32(acc[mi][ni], af[mi], bf[ni]);
        }
        __syncthreads();
    }

    // epilogue + stats partials
    float sL[4], qL[4], sH[4], qH[4];
#pragma unroll
    for (int mi = 0; mi < 4; mi++) { sL[mi]=0.f; qL[mi]=0.f; sH[mi]=0.f; qH[mi]=0.f; }
#pragma unroll
    for (int mi = 0; mi < 4; mi++) {
        int o  = wm + mi*16 + (lane >> 2);
        float bi0 = bias[o];
        float bi1 = bias[o+8];
#pragma unroll
        for (int ni = 0; ni < 4; ni++) {
            int n = n0 + wn + ni*8 + (lane & 3)*2;
            size_t i0 = xbase + (size_t)o*NSP + n;
            size_t i1 = i0 + (size_t)8*NSP;
            float v0 = acc[mi][ni][0] + bi0;
            float v1 = acc[mi][ni][1] + bi0;
            float v2 = acc[mi][ni][2] + bi1;
            float v3 = acc[mi][ni][3] + bi1;
            sL[mi] += v0+v1; qL[mi] += v0*v0+v1*v1;
            sH[mi] += v2+v3; qH[mi] += v2*v2+v3*v3;
            *reinterpret_cast<float2*>(out + i0) = make_float2(v0, v1);
            *reinterpret_cast<float2*>(out + i1) = make_float2(v2, v3);
        }
    }
#pragma unroll
    for (int mi = 0; mi < 4; mi++) {
        sL[mi] += __shfl_xor_sync(0xffffffffu, sL[mi], 1);
        sL[mi] += __shfl_xor_sync(0xffffffffu, sL[mi], 2);
        qL[mi] += __shfl_xor_sync(0xffffffffu, qL[mi], 1);
        qL[mi] += __shfl_xor_sync(0xffffffffu, qL[mi], 2);
        sH[mi] += __shfl_xor_sync(0xffffffffu, sH[mi], 1);
        sH[mi] += __shfl_xor_sync(0xffffffffu, sH[mi], 2);
        qH[mi] += __shfl_xor_sync(0xffffffffu, qH[mi], 1);
        qH[mi] += __shfl_xor_sync(0xffffffffu, qH[mi], 2);
    }
    if ((lane & 3) == 0) {
        int col = wid & 3;
        int rg  = lane >> 2;
#pragma unroll
        for (int mi = 0; mi < 4; mi++) {
            int r = wm + mi*16 + rg;
            redS[r][col] = sL[mi]; redQ[r][col] = qL[mi];
            redS[r+8][col] = sH[mi]; redQ[r+8][col] = qH[mi];
        }
    }
    __syncthreads();
    if (tid < CC) {
        float s = redS[tid][0]+redS[tid][1]+redS[tid][2]+redS[tid][3];
        float q = redQ[tid][0]+redQ[tid][1]+redQ[tid][2]+redQ[tid][3];
        int bc = b*CC + tid;
        ps[bc*NBLK + blockIdx.x] = s;
        pq[bc*NBLK + blockIdx.x] = q;
    }
}

// ---------------- finalize stats: reduce 256 partials per channel ----------------
__global__ __launch_bounds__(256) void finalize_kernel(const float* __restrict__ ps,
                                                       const float* __restrict__ pq,
                                                       float* __restrict__ mu, float* __restrict__ rs)
{
    int e = blockIdx.x, t = threadIdx.x;
    float s = ps[e*NBLK + t];
    float q = pq[e*NBLK + t];
#pragma unroll
    for (int off = 16; off > 0; off >>= 1) {
        s += __shfl_down_sync(0xffffffffu, s, off);
        q += __shfl_down_sync(0xffffffffu, q, off);
    }
    __shared__ float sa[8], sb[8];
    int lane = t & 31, wid = t >> 5;
    if (lane == 0) { sa[wid] = s; sb[wid] = q; }
    __syncthreads();
    if (t == 0) {
        float ts = 0.f, tq = 0.f;
        for (int w = 0; w < 8; w++) { ts += sa[w]; tq += sb[w]; }
        float mean = ts * (1.f/NSP);
        float var  = tq * (1.f/NSP) - mean*mean;
        mu[e] = mean;
        rs[e] = rsqrtf(var + 1e-5f);
    }
}

// ---------------- k/v projections: split-K fp32 (latency-hidden) ----------------
// grid (CC, BQ, KVS), block 128. Each block: one (b,o), K-slice of 128 channels.
__global__ __launch_bounds__(128) void kv_partial(const float* __restrict__ lang,
                                                  const float* __restrict__ wk,
                                                  const float* __restrict__ wv)
{
    int o  = blockIdx.x;
    int b  = blockIdx.y;
    int ks = blockIdx.z;
    int l  = threadIdx.x;
    int c0 = ks * 128;
    const float* lp  = lang + ((size_t)b*CTX + c0)*LSEQ + l;
    const float* wkr = wk + (size_t)o*CTX + c0;
    const float* wvr = wv + (size_t)o*CTX + c0;
    float ka0=0.f, ka1=0.f, ka2=0.f, ka3=0.f;
    float va0=0.f, va1=0.f, va2=0.f, va3=0.f;
#pragma unroll 8
    for (int c = 0; c < 128; c += 4) {
        float x0 = lp[(size_t)(c+0)*LSEQ];
        float x1 = lp[(size_t)(c+1)*LSEQ];
        float x2 = lp[(size_t)(c+2)*LSEQ];
        float x3 = lp[(size_t)(c+3)*LSEQ];
        ka0 = fmaf(wkr[c+0], x0, ka0);
        ka1 = fmaf(wkr[c+1], x1, ka1);
        ka2 = fmaf(wkr[c+2], x2, ka2);
        ka3 = fmaf(wkr[c+3], x3, ka3);
        va0 = fmaf(wvr[c+0], x0, va0);
        va1 = fmaf(wvr[c+1], x1, va1);
        va2 = fmaf(wvr[c+2], x2, va2);
        va3 = fmaf(wvr[c+3], x3, va3);
    }
    size_t pi = (((size_t)b*KVS + ks)*CC + o)*LSEQ + l;
    g_kp[pi] = (ka0 + ka1) + (ka2 + ka3);
    g_vp[pi] = (va0 + va1) + (va2 + va3);
}

// grid (CC, BQ), block 128: sum KVS partials + bias, apply mask
__global__ __launch_bounds__(128) void kv_reduce(const float* __restrict__ mask,
                                                 const float* __restrict__ bk,
                                                 const float* __restrict__ bv)
{
    int o = blockIdx.x;
    int b = blockIdx.y;
    int l = threadIdx.x;
    float ak = bk[o], av = bv[o];
#pragma unroll
    for (int ks = 0; ks < KVS; ks++) {
        size_t pi = (((size_t)b*KVS + ks)*CC + o)*LSEQ + l;
        ak += g_kp[pi];
        av += g_vp[pi];
    }
    float m = mask[b*LSEQ + l];
    g_k[((size_t)b*CC + o)*LSEQ + l] = ak * m;
    g_v[((size_t)b*CC + o)*LSEQ + l] = av * m;
}

// ---------------- attention ----------------
#define SROWP 132
#define ATTN_SMEM_FLOATS (2*HDIM*LSEQ + HDIM + HDIM + LSEQ + 128*SROWP)
__global__ __launch_bounds__(128) void attn_kernel(const float* __restrict__ qbuf,
                                                   const float* __restrict__ mask)
{
    extern __shared__ float sm[];
    float* ks   = sm;
    float* vs   = ks + HDIM*LSEQ;
    float* qmu  = vs + HDIM*LSEQ;
    float* qrs  = qmu + HDIM;
    float* mb   = qrs + HDIM;
    float* simb = mb + LSEQ;
    int bh = blockIdx.y;
    int b = bh >> 2, h = bh & 3;
    int n0 = blockIdx.x * 128;
    int t = threadIdx.x;

    for (int i = t; i < HDIM*LSEQ; i += 128) {
        int idx = (b*CC + h*HDIM + (i >> 7))*LSEQ + (i & 127);
        ks[i] = g_k[idx];
        vs[i] = g_v[idx];
    }
    if (t < HDIM) {
        int ch = b*CC + h*HDIM + t;
        qmu[t] = g_mu[ch];
        qrs[t] = g_rs[ch] * 0.17677669529663687f;   // fold hd^-0.5
    }
    mb[t] = 10000.f * mask[b*LSEQ + t] - 10000.f;
    __syncthreads();

    int n = n0 + t;
    float qv[HDIM];
#pragma unroll
    for (int c = 0; c < HDIM; c++)
        qv[c] = (qbuf[(size_t)(b*CC + h*HDIM + c)*NSP + n] - qmu[c]) * qrs[c];

    float* srow = simb + t*SROWP;
    float mx = -1e30f;
#pragma unroll 2
    for (int l0 = 0; l0 < LSEQ; l0 += 4) {
        float4 m4 = *reinterpret_cast<const float4*>(&mb[l0]);
        float s0 = m4.x, s1 = m4.y, s2 = m4.z, s3 = m4.w;
#pragma unroll
        for (int c = 0; c < HDIM; c++) {
            float4 k4 = *reinterpret_cast<const float4*>(&ks[c*LSEQ + l0]);
            float q = qv[c];
            s0 = fmaf(q, k4.x, s0); s1 = fmaf(q, k4.y, s1);
            s2 = fmaf(q, k4.z, s2); s3 = fmaf(q, k4.w, s3);
        }
        *reinterpret_cast<float4*>(&srow[l0]) = make_float4(s0, s1, s2, s3);
        mx = fmaxf(mx, fmaxf(fmaxf(s0, s1), fmaxf(s2, s3)));
    }
    float ssum = 0.f;
#pragma unroll
    for (int l0 = 0; l0 < LSEQ; l0 += 4) {
        float4 v = *reinterpret_cast<float4*>(&srow[l0]);
        v.x = __expf(v.x - mx); v.y = __expf(v.y - mx);
        v.z = __expf(v.z - mx); v.w = __expf(v.w - mx);
        *reinterpret_cast<float4*>(&srow[l0]) = v;
        ssum += v.x + v.y + v.z + v.w;
    }
    float inv = 1.f / ssum;

    float xa[HDIM];
#pragma unroll
    for (int c = 0; c < HDIM; c++) xa[c] = 0.f;
    for (int l0 = 0; l0 < LSEQ; l0 += 32) {
        float p[32];
#pragma unroll
        for (int j4 = 0; j4 < 8; j4++)
            *reinterpret_cast<float4*>(&p[j4*4]) = *reinterpret_cast<float4*>(&srow[l0 + j4*4]);
#pragma unroll
        for (int c = 0; c < HDIM; c++) {
            float a = xa[c];
#pragma unroll
            for (int j = 0; j < 32; j += 4) {
                float4 v4 = *reinterpret_cast<const float4*>(&vs[c*LSEQ + l0 + j]);
                a = fmaf(p[j],   v4.x, a); a = fmaf(p[j+1], v4.y, a);
                a = fmaf(p[j+2], v4.z, a); a = fmaf(p[j+3], v4.w, a);
            }
            xa[c] = a;
        }
    }
    float* op = g_x + ((size_t)b*NSP + n)*CC + h*HDIM;
#pragma unroll
    for (int c = 0; c < HDIM; c += 4) {
        float4 v4 = make_float4(xa[c]*inv, xa[c+1]*inv, xa[c+2]*inv, xa[c+3]*inv);
        *reinterpret_cast<float4*>(op + c) = v4;
    }
}

// ---------------- fused chain ----------------
__device__ __forceinline__ void chain_frag_a(const uint32_t* sW, uint32_t af[4][4],
                                             int k8, int lane, int wm) {
#pragma unroll
    for (int mi = 0; mi < 4; mi++) {
        int o = wm + mi*16 + (lane >> 2);
        int k = k8 + (lane & 3);
        af[mi][0] = sW[k*SPAD + o];
        af[mi][1] = sW[k*SPAD + o+8];
        af[mi][2] = sW[(k+4)*SPAD + o];
        af[mi][3] = sW[(k+4)*SPAD + o+8];
    }
}

template<int BMODE>   // 0: B is tf32 bits; 1: B is float, convert on load
__device__ __forceinline__ void chain_gemm(const float* __restrict__ Wg, uint32_t* sW,
                                           const uint32_t* sBb, const float* sBf,
                                           float acc[4][4][4],
                                           int tid, int lane, int wm, int wn)
{
#pragma unroll
    for (int mi = 0; mi < 4; mi++)
#pragma unroll
        for (int ni = 0; ni < 4; ni++)
#pragma unroll
            for (int r = 0; r < 4; r++) acc[mi][ni][r] = 0.f;
    for (int k0 = 0; k0 < CC; k0 += 32) {
        stage_w(sW, Wg, k0, tid);
        __syncthreads();
#pragma unroll
        for (int k8 = 0; k8 < 32; k8 += 8) {
            uint32_t af[4][4], bf[4][2];
            chain_frag_a(sW, af, k8, lane, wm);
            int kg = k0 + k8 + (lane & 3);
#pragma unroll
            for (int ni = 0; ni < 4; ni++) {
                int n = wn + ni*8 + (lane >> 2);
                if (BMODE == 0) {
                    bf[ni][0] = sBb[kg*SPAD + n];
                    bf[ni][1] = sBb[(kg+4)*SPAD + n];
                } else {
                    bf[ni][0] = f2tf32(sBf[kg*SPAD + n]);
                    bf[ni][1] = f2tf32(sBf[(kg+4)*SPAD + n]);
                }
            }
#pragma unroll
            for (int mi = 0; mi < 4; mi++)
#pragma unroll
                for (int ni = 0; ni < 4; ni++)
                    mma_tf32(acc[mi][ni], af[mi], bf[ni]);
        }
        __syncthreads();
    }
}

__global__ __launch_bounds__(256) void chain_kernel(
    const float* __restrict__ SKIP, const float* __restrict__ WB,
    const float* __restrict__ mu1, const float* __restrict__ rs1,
    const float* __restrict__ mu2, const float* __restrict__ rs2,
    const float* __restrict__ wpo, const float* __restrict__ bpo,
    const float* __restrict__ wg1, const float* __restrict__ bg1,
    const float* __restrict__ wg2, const float* __restrict__ bg2,
    float* __restrict__ out)
{
    extern __shared__ char smraw[];
    uint32_t* sW = reinterpret_cast<uint32_t*>(smraw);                       // [32][136]
    uint32_t* sB = reinterpret_cast<uint32_t*>(smraw + 32*SPAD*4);           // [128][136] tf32
    float*    sO = reinterpret_cast<float*>   (smraw + (32+128)*SPAD*4);     // [128][136] fp32
    float*    sBf = reinterpret_cast<float*>(sB);

    const int b   = blockIdx.y;
    const int n0  = blockIdx.x * 128;
    const int tid = threadIdx.x;
    const int lane = tid & 31;
    const int wid  = tid >> 5;
    const int wm = (wid >> 2) * 64;
    const int wn = (wid & 3) * 32;
    const size_t xbase = (size_t)b * CC * NSP;

    {
        int n4  = (tid & 31) * 4;
        int kkb = tid >> 5;
#pragma unroll
        for (int r = 0; r < 16; r++) {
            int c = kkb + 8*r;
            size_t gi = xbase + (size_t)c*NSP + n0 + n4;
            int sc = b*CC + c;
            float m1 = mu1[sc], r1 = rs1[sc], m2 = mu2[sc], r2 = rs2[sc];
            float4 v  = *reinterpret_cast<const float4*>(SKIP + gi);
            float4 v2 = *reinterpret_cast<const float4*>(WB + gi);
            v.x = ((v.x - m1)*r1) * ((v2.x - m2)*r2);
            v.y = ((v.y - m1)*r1) * ((v2.y - m2)*r2);
            v.z = ((v.z - m1)*r1) * ((v2.z - m2)*r2);
            v.w = ((v.w - m1)*r1) * ((v2.w - m2)*r2);
            uint4 u = make_uint4(f2tf32(v.x), f2tf32(v.y), f2tf32(v.z), f2tf32(v.w));
            *reinterpret_cast<uint4*>(&sB[c*SPAD + n4]) = u;
        }
    }
    __syncthreads();

    float acc[4][4][4];

    // GEMM1: out = relu(wpo @ sB + bpo) -> sO (fp32)
    chain_gemm<0>(wpo, sW, sB, nullptr, acc, tid, lane, wm, wn);
#pragma unroll
    for (int mi = 0; mi < 4; mi++) {
        int o = wm + mi*16 + (lane >> 2);
        float bi0 = bpo[o], bi1 = bpo[o+8];
#pragma unroll
        for (int ni = 0; ni < 4; ni++) {
            int n = wn + ni*8 + (lane & 3)*2;
            sO[o*SPAD + n]     = fmaxf(acc[mi][ni][0] + bi0, 0.f);
            sO[o*SPAD + n+1]   = fmaxf(acc[mi][ni][1] + bi0, 0.f);
            sO[(o+8)*SPAD + n]   = fmaxf(acc[mi][ni][2] + bi1, 0.f);
            sO[(o+8)*SPAD + n+1] = fmaxf(acc[mi][ni][3] + bi1, 0.f);
        }
    }
    __syncthreads();

    // GEMM2: t = relu(wg1 @ sO + bg1) -> sB
    chain_gemm<1>(wg1, sW, nullptr, sO, acc, tid, lane, wm, wn);
#pragma unroll
    for (int mi = 0; mi < 4; mi++) {
        int o = wm + mi*16 + (lane >> 2);
        float bi0 = bg1[o], bi1 = bg1[o+8];
#pragma unroll
        for (int ni = 0; ni < 4; ni++) {
            int n = wn + ni*8 + (lane & 3)*2;
            sB[o*SPAD + n]     = f2tf32(fmaxf(acc[mi][ni][0] + bi0, 0.f));
            sB[o*SPAD + n+1]   = f2tf32(fmaxf(acc[mi][ni][1] + bi0, 0.f));
            sB[(o+8)*SPAD + n]   = f2tf32(fmaxf(acc[mi][ni][2] + bi1, 0.f));
            sB[(o+8)*SPAD + n+1] = f2tf32(fmaxf(acc[mi][ni][3] + bi1, 0.f));
        }
    }
    __syncthreads();

    // GEMM3: final = tanh(wg2 @ sB + bg2) * sO -> global out
    chain_gemm<0>(wg2, sW, sB, nullptr, acc, tid, lane, wm, wn);
#pragma unroll
    for (int mi = 0; mi < 4; mi++) {
        int o = wm + mi*16 + (lane >> 2);
        float bi0 = bg2[o], bi1 = bg2[o+8];
#pragma unroll
        for (int ni = 0; ni < 4; ni++) {
            int n = wn + ni*8 + (lane & 3)*2;
            size_t i0 = xbase + (size_t)o*NSP + n0 + n;
            size_t i1 = i0 + (size_t)8*NSP;
            float v0 = tanhf(acc[mi][ni][0] + bi0) * sO[o*SPAD + n];
            float v1 = tanhf(acc[mi][ni][1] + bi0) * sO[o*SPAD + n+1];
            float v2 = tanhf(acc[mi][ni][2] + bi1) * sO[(o+8)*SPAD + n];
            float v3 = tanhf(acc[mi][ni][3] + bi1) * sO[(o+8)*SPAD + n+1];
            *reinterpret_cast<float2*>(out + i0) = make_float2(v0, v1);
            *reinterpret_cast<float2*>(out + i1) = make_float2(v2, v3);
        }
    }
}

// ---------------- host orchestration ----------------
extern "C" void kernel_launch(void* const* d_in, const int* in_sizes, int n_in,
                              void* d_out, int out_size)
{
    const float* img  = (const float*)d_in[0];
    const float* lang = (const float*)d_in[1];
    const float* mask = (const float*)d_in[2];
    const float* wq   = (const float*)d_in[3];
    const float* bq   = (const float*)d_in[4];
    const float* wk   = (const float*)d_in[5];
    const float* bk   = (const float*)d_in[6];
    const float* wv   = (const float*)d_in[7];
    const float* bv   = (const float*)d_in[8];
    const float* wpw  = (const float*)d_in[9];
    const float* bpw  = (const float*)d_in[10];
    const float* wpi  = (const float*)d_in[11];
    const float* bpi  = (const float*)d_in[12];
    const float* wpo  = (const float*)d_in[13];
    const float* bpo  = (const float*)d_in[14];
    const float* wg1  = (const float*)d_in[15];
    const float* bg1  = (const float*)d_in[16];
    const float* wg2  = (const float*)d_in[17];
    const float* bg2  = (const float*)d_in[18];
    float* out = (float*)d_out;

    void *pq, *pskip, *px, *pw, *pmu, *prs, *pps, *ppq;
    cudaGetSymbolAddress(&pq,   g_q);
    cudaGetSymbolAddress(&pskip,g_skip);
    cudaGetSymbolAddress(&px,   g_x);
    cudaGetSymbolAddress(&pw,   g_w);
    cudaGetSymbolAddress(&pmu,  g_mu);
    cudaGetSymbolAddress(&prs,  g_rs);
    cudaGetSymbolAddress(&pps,  g_ps);
    cudaGetSymbolAddress(&ppq,  g_pq2);
    float* Q    = (float*)pq;
    float* SKIP = (float*)pskip;
    float* X    = (float*)px;
    float* WB   = (float*)pw;
    float* MU   = (float*)pmu;
    float* RS   = (float*)prs;
    float* PS   = (float*)pps;
    float* PQ   = (float*)ppq;

    const int attn_smem  = ATTN_SMEM_FLOATS * (int)sizeof(float);
    const int chain_smem = (32 + 128)*SPAD*4 + 128*SPAD*4;   // sW + sB + sO
    cudaFuncSetAttribute(attn_kernel,  cudaFuncAttributeMaxDynamicSharedMemorySize, attn_smem);
    cudaFuncSetAttribute(chain_kernel, cudaFuncAttributeMaxDynamicSharedMemorySize, chain_smem);

    dim3 gg(NBLK, BQ);
    const int E = BQ*CC;   // entries per stats slot

    // producers (stats partials in epilogue)
    gemm_tc<<<gg,256>>>(img, wq,  bq,  Q,    PS + 0*E*NBLK, PQ + 0*E*NBLK);
    gemm_tc<<<gg,256>>>(img, wpi, bpi, SKIP, PS + 1*E*NBLK, PQ + 1*E*NBLK);
    finalize_kernel<<<2*E,256>>>(PS, PQ, MU, RS);           // slots 0,1

    kv_partial<<<dim3(CC,BQ,KVS),128>>>(lang, wk, wv);
    kv_reduce <<<dim3(CC,BQ),128>>>(mask, bk, bv);

    attn_kernel<<<dim3(NBLK, BQ*NHEAD), 128, attn_smem>>>(Q, mask);

    gemm_tc<<<gg,256>>>(X, wpw, bpw, WB, PS + 2*E*NBLK, PQ + 2*E*NBLK);
    finalize_kernel<<<E,256>>>(PS + 2*E*NBLK, PQ + 2*E*NBLK, MU + 2*E, RS + 2*E);   // slot 2

    chain_kernel<<<gg,256,chain_smem>>>(SKIP, WB,
                                        MU + 1*E, RS + 1*E, MU + 2*E, RS + 2*E,
                                        wpo, bpo, wg1, bg1, wg2, bg2, out);
}